// round 15
// baseline (speedup 1.0000x reference)
#include <cuda_runtime.h>
#include <math.h>

// HydraChannelMixer — GB300 sm_103a, SMEM-staged weights + register-row tiling.
// 2 tiles [C=32, D=128] per 256-thread block, grid = 8192.

#define NT   256
#define GRID 8192

struct __align__(16) Tile {
    float h[32][132];    // raw h tile (pitch 132)
    float low[32][36];   // h_low, later overwritten by Qn*cg (pitch 36)
    float kv[32][36];    // Kn*V rows
    float gin[260];      // gate input [257]
    float mu[32];
    float rstd[32];
    float gf[32];        // global_feat
    float g1p[4][32];    // Wg1 partials
    float g1[32];
    float gate[144];     // gate, skewed layout: [q*36 + o]
    float pad[28];       // keeps sizeof(Tile) ≡ 16 words (mod 32) for bank separation
};

struct __align__(16) Smem {
    float Wd[128][32];   // gamma-folded W_down
    float We[32][148];   // [k][q*36+o] : q in {Q,K,V,CG}
    float Wu[32][148];   // [r][q*36+o] : W_up columns 32q+o
    float cS1[32];       // sum_d gamma*W_down
    float cS2f[32];      // sum_d beta*W_down + b_down
    Tile tile[2];
};

__global__ void __launch_bounds__(NT, 2) hydra_kernel(
    const float* __restrict__ x,
    const float* __restrict__ gamma,
    const float* __restrict__ beta,
    const float* __restrict__ W_down,
    const float* __restrict__ b_down,
    const float* __restrict__ W_q,
    const float* __restrict__ W_k,
    const float* __restrict__ W_v,
    const float* __restrict__ W_cg,
    const float* __restrict__ b_cg,
    const float* __restrict__ W_up,
    const float* __restrict__ b_up,
    const float* __restrict__ Wg1,
    const float* __restrict__ bg1,
    const float* __restrict__ Wg2,
    const float* __restrict__ bg2,
    float* __restrict__ out)
{
    extern __shared__ __align__(16) char smem_raw[];
    Smem& S = *reinterpret_cast<Smem*>(smem_raw);

    const int t    = threadIdx.x;
    const int lane = t & 31;
    const int w    = t >> 5;
    const unsigned FULL = 0xffffffffu;

    // cS partials parked in tile[].kv (unused until P3)
    float* cp1 = &S.tile[0].kv[0][0];
    float* cp2 = &S.tile[1].kv[0][0];

    // ================= P0: stage weights + both h tiles =================
    #pragma unroll
    for (int i = 0; i < 16; i++) {
        int idx = i * NT + t;
        int d = idx >> 5, r = idx & 31;
        S.Wd[d][r] = __ldg(gamma + d) * __ldg(W_down + idx);
    }
    {
        int o  = t & 31;
        int mq = (t >> 5) & 3;                 // uniform per warp
        const float* Wm = (mq == 0) ? W_q : (mq == 1) ? W_k : (mq == 2) ? W_v : W_cg;
        #pragma unroll
        for (int i = 0; i < 16; i++) {
            int k = i * 2 + (t >> 7);
            S.We[k][mq * 36 + o] = __ldg(Wm + k * 32 + o);
            S.Wu[k][mq * 36 + o] = __ldg(W_up + k * 128 + mq * 32 + o);
        }
    }
    {
        const float4* x4 = (const float4*)x;
        #pragma unroll
        for (int i = 0; i < 8; i++) {
            int g = i * NT + t;
            int tl = g >> 10, loc = g & 1023;
            int c = loc >> 5, v = loc & 31;
            int bp = blockIdx.x * 2 + tl;
            int b = bp >> 8, p = bp & 255;
            *(float4*)&S.tile[tl].h[c][v * 4] = x4[(b * 8192 + c * 256 + p) * 32 + v];
        }
    }
    {   // cS1/cS2 partials (pure LDG)
        int r = t & 31, ch = t >> 5;
        float s1 = 0.f, s2 = 0.f;
        #pragma unroll 4
        for (int dd = 0; dd < 16; dd++) {
            int d = ch * 16 + dd;
            float wv = __ldg(W_down + d * 32 + r);
            s1 = fmaf(__ldg(gamma + d), wv, s1);
            s2 = fmaf(__ldg(beta  + d), wv, s2);
        }
        cp1[ch * 32 + r] = s1;
        cp2[ch * 32 + r] = s2;
    }
    __syncthreads();

    // ================= P1: LN row stats + channel stats + cS finalize =================
    if (w < 4) {
        Tile& T = S.tile[w >> 1];
        int c0 = (w & 1) * 16;
        #pragma unroll 2
        for (int i = 0; i < 16; i++) {
            int c = c0 + i;
            float s = 0.f, ss = 0.f;
            #pragma unroll
            for (int u = 0; u < 4; u++) {
                float v = T.h[c][lane + 32 * u];
                s += v; ss = fmaf(v, v, ss);
            }
            #pragma unroll
            for (int off = 16; off >= 1; off >>= 1) {
                s  += __shfl_xor_sync(FULL, s,  off);
                ss += __shfl_xor_sync(FULL, ss, off);
            }
            if (lane == 0) {
                float mu  = s * 0.0078125f;
                float var = ss * 0.0078125f - mu * mu;
                T.mu[c]   = mu;
                T.rstd[c] = rsqrtf(var + 1e-5f);
            }
        }
    } else {
        int wi = w - 4;
        Tile& T = S.tile[wi >> 1];
        int d1 = (wi & 1) * 32 + lane;
        int d2 = d1 + 64;
        float s1=0.f, ss1=0.f, sa1=0.f, s2=0.f, ss2=0.f, sa2=0.f;
        #pragma unroll 8
        for (int c = 0; c < 32; c++) {
            float v1 = T.h[c][d1];
            float v2 = T.h[c][d2];
            s1 += v1; ss1 = fmaf(v1, v1, ss1); sa1 += fabsf(v1);
            s2 += v2; ss2 = fmaf(v2, v2, ss2); sa2 += fabsf(v2);
        }
        T.gin[d1]       = (ss1 - s1 * s1 * 0.03125f) * (1.f / 31.f);
        T.gin[128 + d1] = sa1 * 0.03125f;
        T.gin[d2]       = (ss2 - s2 * s2 * 0.03125f) * (1.f / 31.f);
        T.gin[128 + d2] = sa2 * 0.03125f;
        if ((wi & 1) == 0 && lane == 0) T.gin[256] = 0.501716659f;  // log(32)/log(1000)
    }
    if (t < 32) {
        float s = 0.f;
        #pragma unroll
        for (int ch = 0; ch < 8; ch++) s += cp1[ch * 32 + t];
        S.cS1[t] = s;
    } else if (t < 64) {
        int r = t - 32;
        float s = __ldg(b_down + r);
        #pragma unroll
        for (int ch = 0; ch < 8; ch++) s += cp2[ch * 32 + r];
        S.cS2f[r] = s;
    }
    __syncthreads();

    // ================= P2: down-proj for BOTH tiles (LN folded) =================
    {
        int c = t >> 3, rq = t & 7;
        float4 a0 = make_float4(0.f,0.f,0.f,0.f);
        float4 a1 = make_float4(0.f,0.f,0.f,0.f);
        #pragma unroll 4
        for (int d = 0; d < 128; d++) {
            float4 wv = *(const float4*)&S.Wd[d][rq * 4];
            float h0 = S.tile[0].h[c][d];
            float h1 = S.tile[1].h[c][d];
            a0.x = fmaf(h0, wv.x, a0.x); a0.y = fmaf(h0, wv.y, a0.y);
            a0.z = fmaf(h0, wv.z, a0.z); a0.w = fmaf(h0, wv.w, a0.w);
            a1.x = fmaf(h1, wv.x, a1.x); a1.y = fmaf(h1, wv.y, a1.y);
            a1.z = fmaf(h1, wv.z, a1.z); a1.w = fmaf(h1, wv.w, a1.w);
        }
        float4 cs1 = *(const float4*)&S.cS1[rq * 4];
        float4 cs2 = *(const float4*)&S.cS2f[rq * 4];
        {
            Tile& T = S.tile[0];
            float mu = T.mu[c], rs = T.rstd[c];
            float4 o;
            o.x = fmaf(rs, fmaf(-mu, cs1.x, a0.x), cs2.x);
            o.y = fmaf(rs, fmaf(-mu, cs1.y, a0.y), cs2.y);
            o.z = fmaf(rs, fmaf(-mu, cs1.z, a0.z), cs2.z);
            o.w = fmaf(rs, fmaf(-mu, cs1.w, a0.w), cs2.w);
            *(float4*)&T.low[c][rq * 4] = o;
        }
        {
            Tile& T = S.tile[1];
            float mu = T.mu[c], rs = T.rstd[c];
            float4 o;
            o.x = fmaf(rs, fmaf(-mu, cs1.x, a1.x), cs2.x);
            o.y = fmaf(rs, fmaf(-mu, cs1.y, a1.y), cs2.y);
            o.z = fmaf(rs, fmaf(-mu, cs1.z, a1.z), cs2.z);
            o.w = fmaf(rs, fmaf(-mu, cs1.w, a1.w), cs2.w);
            *(float4*)&T.low[c][rq * 4] = o;
        }
    }
    __syncthreads();

    // ================= P3: Q/K/V/CG — one full output row per thread =================
    {
        int c  = t >> 3;
        int qh = t & 7;
        int q  = qh & 3;       // 0=Q 1=K 2=V 3=CG
        int tl = qh >> 2;
        Tile& T = S.tile[tl];

        float acc[32];
        #pragma unroll
        for (int i = 0; i < 32; i++) acc[i] = 0.f;

        #pragma unroll 4
        for (int k = 0; k < 32; k++) {
            float hv = T.low[c][k];
            const float4* wr = (const float4*)&S.We[k][q * 36];
            #pragma unroll
            for (int j = 0; j < 8; j++) {
                float4 wv = wr[j];
                acc[4*j+0] = fmaf(hv, wv.x, acc[4*j+0]);
                acc[4*j+1] = fmaf(hv, wv.y, acc[4*j+1]);
                acc[4*j+2] = fmaf(hv, wv.z, acc[4*j+2]);
                acc[4*j+3] = fmaf(hv, wv.w, acc[4*j+3]);
            }
        }
        // in-thread l2norm for Q/K rows
        float s = 0.f;
        #pragma unroll
        for (int i = 0; i < 32; i++) s = fmaf(acc[i], acc[i], s);
        float rs  = 1.f / fmaxf(sqrtf(s), 1e-12f);
        float nrm = (q <= 1) ? rs : 1.f;
        #pragma unroll
        for (int i = 0; i < 32; i++) acc[i] *= nrm;

        int srck = (lane & ~3) | 1;   // K lane of this group
        int srcg = lane | 3;          // CG lane of this group
        #pragma unroll
        for (int j = 0; j < 8; j++) {   // Kn*V rows (stored by V lanes)
            float4 pv;
            pv.x = __shfl_sync(FULL, acc[4*j+0], srck) * acc[4*j+0];
            pv.y = __shfl_sync(FULL, acc[4*j+1], srck) * acc[4*j+1];
            pv.z = __shfl_sync(FULL, acc[4*j+2], srck) * acc[4*j+2];
            pv.w = __shfl_sync(FULL, acc[4*j+3], srck) * acc[4*j+3];
            if (q == 2) *(float4*)&T.kv[c][4*j] = pv;
        }
        #pragma unroll
        for (int j = 0; j < 8; j++) {   // cg sigmoid -> Q lanes store Qn*cg over low
            float4 bc = __ldg((const float4*)b_cg + j);
            float4 cg4;
            cg4.x = 1.f / (1.f + __expf(-(acc[4*j+0] + bc.x)));
            cg4.y = 1.f / (1.f + __expf(-(acc[4*j+1] + bc.y)));
            cg4.z = 1.f / (1.f + __expf(-(acc[4*j+2] + bc.z)));
            cg4.w = 1.f / (1.f + __expf(-(acc[4*j+3] + bc.w)));
            float4 qa;
            qa.x = acc[4*j+0] * __shfl_sync(FULL, cg4.x, srcg);
            qa.y = acc[4*j+1] * __shfl_sync(FULL, cg4.y, srcg);
            qa.z = acc[4*j+2] * __shfl_sync(FULL, cg4.z, srcg);
            qa.w = acc[4*j+3] * __shfl_sync(FULL, cg4.w, srcg);
            if (q == 0) *(float4*)&T.low[c][4*j] = qa;
        }
    }
    __syncthreads();

    // ================= P4: Wg1 partials + global_feat reduce =================
    {
        int tl = t >> 7, u = t & 127;
        Tile& T = S.tile[tl];
        int j = u & 31, ch = u >> 5;
        int i0 = ch * 64;
        float s = 0.f;
        #pragma unroll 4
        for (int i = 0; i < 64; i++)
            s = fmaf(T.gin[i0 + i], __ldg(Wg1 + (i0 + i) * 32 + j), s);
        if (ch == 3)
            s = fmaf(T.gin[256], __ldg(Wg1 + 256 * 32 + j), s);
        T.g1p[ch][j] = s;
        if (u < 32) {
            float g = 0.f;
            #pragma unroll 8
            for (int c = 0; c < 32; c++) g += T.kv[c][u];
            T.gf[u] = g;
        }
    }
    __syncthreads();

    // ================= P5: g1 (gelu) + prescale qa *= gf =================
    {
        int tl = t >> 7, u = t & 127;
        Tile& T = S.tile[tl];
        if (u < 32) {
            float s = __ldg(bg1 + u);
            #pragma unroll
            for (int ch = 0; ch < 4; ch++) s += T.g1p[ch][u];
            T.g1[u] = 0.5f * s * (1.f + erff(s * 0.7071067811865475f));
        }
        int c = u >> 2, rq = u & 3;
        float4 ga = *(const float4*)&T.gf[rq * 8];
        float4 gb = *(const float4*)&T.gf[rq * 8 + 4];
        float4 qa = *(const float4*)&T.low[c][rq * 8];
        float4 qb = *(const float4*)&T.low[c][rq * 8 + 4];
        qa.x *= ga.x; qa.y *= ga.y; qa.z *= ga.z; qa.w *= ga.w;
        qb.x *= gb.x; qb.y *= gb.y; qb.z *= gb.z; qb.w *= gb.w;
        *(float4*)&T.low[c][rq * 8]     = qa;
        *(float4*)&T.low[c][rq * 8 + 4] = qb;
    }
    __syncthreads();

    // ================= P6: gate2 (sigmoid) =================
    {
        int tl = t >> 7, u = t & 127;
        Tile& T = S.tile[tl];
        float s = __ldg(bg2 + u);
        #pragma unroll 8
        for (int j = 0; j < 32; j++)
            s = fmaf(T.g1[j], __ldg(Wg2 + j * 128 + u), s);
        T.gate[(u >> 5) * 36 + (u & 31)] = 1.f / (1.f + __expf(-s));  // skewed layout
    }
    __syncthreads();

    // ================= P7: up-proj + gated residual (into smem h) =================
    {
        int c  = t >> 3;
        int qh = t & 7;
        int q  = qh & 3;
        int tl = qh >> 2;
        Tile& T = S.tile[tl];

        float4 A[8];
        #pragma unroll
        for (int j = 0; j < 8; j++) A[j] = make_float4(0.f,0.f,0.f,0.f);

        #pragma unroll 4
        for (int r = 0; r < 32; r++) {
            float av = T.low[c][r];
            const float4* wr = (const float4*)&S.Wu[r][q * 36];
            #pragma unroll
            for (int j = 0; j < 8; j++) {
                float4 wv = wr[j];
                A[j].x = fmaf(av, wv.x, A[j].x);
                A[j].y = fmaf(av, wv.y, A[j].y);
                A[j].z = fmaf(av, wv.z, A[j].z);
                A[j].w = fmaf(av, wv.w, A[j].w);
            }
        }
        const float4* gt4 = (const float4*)&T.gate[q * 36];
        #pragma unroll
        for (int j = 0; j < 8; j++) {
            float4 hv = *(const float4*)&T.h[c][q * 32 + 4*j];
            float4 gt = gt4[j];
            float4 bu = __ldg((const float4*)b_up + q * 8 + j);
            float4 o;
            o.x = fmaf(gt.x, A[j].x + bu.x, hv.x);
            o.y = fmaf(gt.y, A[j].y + bu.y, hv.y);
            o.z = fmaf(gt.z, A[j].z + bu.z, hv.z);
            o.w = fmaf(gt.w, A[j].w + bu.w, hv.w);
            *(float4*)&T.h[c][q * 32 + 4*j] = o;
        }
    }
    __syncthreads();

    // ================= P8: coalesced store =================
    {
        float4* out4 = (float4*)out;
        #pragma unroll
        for (int i = 0; i < 8; i++) {
            int g = i * NT + t;
            int tl = g >> 10, loc = g & 1023;
            int c = loc >> 5, v = loc & 31;
            int bp = blockIdx.x * 2 + tl;
            int b = bp >> 8, p = bp & 255;
            out4[(b * 8192 + c * 256 + p) * 32 + v] = *(const float4*)&S.tile[tl].h[c][v * 4];
        }
    }
}

extern "C" void kernel_launch(void* const* d_in, const int* in_sizes, int n_in,
                              void* d_out, int out_size)
{
    const float* x      = (const float*)d_in[0];
    const float* gamma  = (const float*)d_in[1];
    const float* beta   = (const float*)d_in[2];
    const float* W_down = (const float*)d_in[3];
    const float* b_down = (const float*)d_in[4];
    const float* W_q    = (const float*)d_in[5];
    const float* W_k    = (const float*)d_in[6];
    const float* W_v    = (const float*)d_in[7];
    const float* W_cg   = (const float*)d_in[8];
    const float* b_cg   = (const float*)d_in[9];
    const float* W_up   = (const float*)d_in[10];
    const float* b_up   = (const float*)d_in[11];
    const float* Wg1    = (const float*)d_in[12];
    const float* bg1    = (const float*)d_in[13];
    const float* Wg2    = (const float*)d_in[14];
    const float* bg2    = (const float*)d_in[15];

    cudaFuncSetAttribute(hydra_kernel, cudaFuncAttributeMaxDynamicSharedMemorySize,
                         (int)sizeof(Smem));
    hydra_kernel<<<GRID, NT, sizeof(Smem)>>>(x, gamma, beta, W_down, b_down,
                                             W_q, W_k, W_v, W_cg, b_cg,
                                             W_up, b_up, Wg1, bg1, Wg2, bg2,
                                             (float*)d_out);
}

// round 16
// speedup vs baseline: 1.4395x; 1.4395x over previous
#include <cuda_runtime.h>
#include <math.h>

// HydraChannelMixer — GB300 sm_103a, round 16.
// 2 tiles [C=32, D=128] per 256-thread block (grid 8192), SMEM-staged weights,
// 2-D register-tiled GEMMs with packed fma.rn.f32x2.

#define NT   256
#define GRID 8192

typedef unsigned long long ull;
union F2 { ull u; float2 f; };

__device__ __forceinline__ ull dup2(float a) {
    ull r; asm("mov.b64 %0, {%1, %1};" : "=l"(r) : "f"(a)); return r;
}
__device__ __forceinline__ void fma2(ull& d, ull a, ull b) {
    asm("fma.rn.f32x2 %0, %1, %2, %0;" : "+l"(d) : "l"(a), "l"(b));
}

struct __align__(16) Smem {
    float Wd[128][32];    // gamma-folded W_down (k-major)
    float We[32][144];    // [k][q*36+o], q in {Q,K,V,CG}
    float Wu[32][144];    // [k][q*36+o], W_up col q*32+o
    float cS1[32];        // sum_d gamma*W_down
    float cS2f[32];       // sum_d beta*W_down + b_down
    float h[2][32][132];  // raw h tiles
    float low[64][36];    // h_low rows (row = tl*32+c); cp partials live here pre-P2
    float qa[64][36];     // Qn*cg rows, later scaled by gf
    float kvgate[576];    // kvp[16][36] (P3-P4), then gate[2][144] (P6-P7)
    float gin[2][260];    // gate-MLP input
    float mu2[64];
    float rstd2[64];
    float gf[2][32];      // global_feat
    float g1p[2][4][32];  // Wg1 partials
    float g1[2][32];
};

__global__ void __launch_bounds__(NT, 2) hydra_kernel(
    const float* __restrict__ x,
    const float* __restrict__ gamma,
    const float* __restrict__ beta,
    const float* __restrict__ W_down,
    const float* __restrict__ b_down,
    const float* __restrict__ W_q,
    const float* __restrict__ W_k,
    const float* __restrict__ W_v,
    const float* __restrict__ W_cg,
    const float* __restrict__ b_cg,
    const float* __restrict__ W_up,
    const float* __restrict__ b_up,
    const float* __restrict__ Wg1,
    const float* __restrict__ bg1,
    const float* __restrict__ Wg2,
    const float* __restrict__ bg2,
    float* __restrict__ out)
{
    extern __shared__ __align__(16) char smem_raw[];
    Smem& S = *reinterpret_cast<Smem*>(smem_raw);

    const int t    = threadIdx.x;
    const int lane = t & 31;
    const int w    = t >> 5;
    const unsigned FULL = 0xffffffffu;

    float* cp = &S.low[0][0];   // [2][8][32] cS partials, dead before P2

    // ================= P0: stage weights + both h tiles + cS partials ============
    #pragma unroll
    for (int i = 0; i < 16; i++) {
        int idx = i * NT + t;
        int d = idx >> 5, r = idx & 31;
        S.Wd[d][r] = __ldg(gamma + d) * __ldg(W_down + idx);
    }
    {
        int o  = t & 31;
        int mq = (t >> 5) & 3;      // uniform per warp
        const float* Wm = (mq == 0) ? W_q : (mq == 1) ? W_k : (mq == 2) ? W_v : W_cg;
        #pragma unroll
        for (int i = 0; i < 16; i++) {
            int k = i * 2 + (t >> 7);
            S.We[k][mq * 36 + o] = __ldg(Wm + k * 32 + o);
            S.Wu[k][mq * 36 + o] = __ldg(W_up + k * 128 + mq * 32 + o);
        }
    }
    {
        const float4* x4 = (const float4*)x;
        #pragma unroll
        for (int i = 0; i < 8; i++) {
            int g = i * NT + t;
            int tl = g >> 10, loc = g & 1023;
            int c = loc >> 5, v = loc & 31;
            int bp = blockIdx.x * 2 + tl;
            int b = bp >> 8, p = bp & 255;
            *(float4*)&S.h[tl][c][v * 4] = x4[(b * 8192 + c * 256 + p) * 32 + v];
        }
    }
    {
        int r = t & 31, ch = t >> 5;
        float s1 = 0.f, s2 = 0.f;
        #pragma unroll 4
        for (int dd = 0; dd < 16; dd++) {
            int d = ch * 16 + dd;
            float wv = __ldg(W_down + d * 32 + r);
            s1 = fmaf(__ldg(gamma + d), wv, s1);
            s2 = fmaf(__ldg(beta  + d), wv, s2);
        }
        cp[ch * 32 + r]       = s1;
        cp[256 + ch * 32 + r] = s2;
    }
    __syncthreads();

    // ================= P1: LN row stats + channel stats + cS finalize ============
    if (w < 4) {
        int tl = w >> 1, c0 = (w & 1) * 16;
        #pragma unroll 2
        for (int i = 0; i < 16; i++) {
            int c = c0 + i;
            float s = 0.f, ss = 0.f;
            #pragma unroll
            for (int u = 0; u < 4; u++) {
                float v = S.h[tl][c][lane + 32 * u];
                s += v; ss = fmaf(v, v, ss);
            }
            #pragma unroll
            for (int off = 16; off >= 1; off >>= 1) {
                s  += __shfl_xor_sync(FULL, s,  off);
                ss += __shfl_xor_sync(FULL, ss, off);
            }
            if (lane == 0) {
                float mu  = s * 0.0078125f;
                float var = ss * 0.0078125f - mu * mu;
                S.mu2[tl * 32 + c]   = mu;
                S.rstd2[tl * 32 + c] = rsqrtf(var + 1e-5f);
            }
        }
    } else {
        int wi = w - 4;
        int tl = wi >> 1;
        int d1 = (wi & 1) * 32 + lane;
        int d2 = d1 + 64;
        float s1=0.f, ss1=0.f, sa1=0.f, s2=0.f, ss2=0.f, sa2=0.f;
        #pragma unroll 8
        for (int c = 0; c < 32; c++) {
            float v1 = S.h[tl][c][d1];
            float v2 = S.h[tl][c][d2];
            s1 += v1; ss1 = fmaf(v1, v1, ss1); sa1 += fabsf(v1);
            s2 += v2; ss2 = fmaf(v2, v2, ss2); sa2 += fabsf(v2);
        }
        S.gin[tl][d1]       = (ss1 - s1 * s1 * 0.03125f) * (1.f / 31.f);
        S.gin[tl][128 + d1] = sa1 * 0.03125f;
        S.gin[tl][d2]       = (ss2 - s2 * s2 * 0.03125f) * (1.f / 31.f);
        S.gin[tl][128 + d2] = sa2 * 0.03125f;
        if ((wi & 1) == 0 && lane == 0) S.gin[tl][256] = 0.501716659f; // log32/log1000
    }
    if (t < 32) {
        float s = 0.f;
        #pragma unroll
        for (int ch = 0; ch < 8; ch++) s += cp[ch * 32 + t];
        S.cS1[t] = s;
    } else if (t < 64) {
        int r = t - 32;
        float s = __ldg(b_down + r);
        #pragma unroll
        for (int ch = 0; ch < 8; ch++) s += cp[256 + ch * 32 + r];
        S.cS2f[r] = s;
    }
    __syncthreads();

    // ================= P2: down-proj (LN folded), r=2 x c=4 tiles ================
    {
        int rowg = t >> 3, colg = t & 7;
        int r0 = rowg * 2, r1 = r0 + 1;
        int tl = rowg >> 4;
        int cA = r0 & 31, cB = cA + 1;
        ull acc00 = 0, acc01 = 0, acc10 = 0, acc11 = 0;
        #pragma unroll
        for (int kc = 0; kc < 8; kc++) {
            float a0[16], a1[16];
            #pragma unroll
            for (int qd = 0; qd < 4; qd++) {
                *(float4*)&a0[qd * 4] = *(const float4*)&S.h[tl][cA][kc * 16 + qd * 4];
                *(float4*)&a1[qd * 4] = *(const float4*)&S.h[tl][cB][kc * 16 + qd * 4];
            }
            #pragma unroll
            for (int kk = 0; kk < 16; kk++) {
                ulonglong2 b2 = *(const ulonglong2*)&S.Wd[kc * 16 + kk][colg * 4];
                ull d0 = dup2(a0[kk]), d1 = dup2(a1[kk]);
                fma2(acc00, d0, b2.x); fma2(acc01, d0, b2.y);
                fma2(acc10, d1, b2.x); fma2(acc11, d1, b2.y);
            }
        }
        float4 cs1 = *(const float4*)&S.cS1[colg * 4];
        float4 cs2 = *(const float4*)&S.cS2f[colg * 4];
        {
            float mu = S.mu2[r0], rs = S.rstd2[r0];
            F2 u0, u1; u0.u = acc00; u1.u = acc01;
            float4 o;
            o.x = fmaf(rs, fmaf(-mu, cs1.x, u0.f.x), cs2.x);
            o.y = fmaf(rs, fmaf(-mu, cs1.y, u0.f.y), cs2.y);
            o.z = fmaf(rs, fmaf(-mu, cs1.z, u1.f.x), cs2.z);
            o.w = fmaf(rs, fmaf(-mu, cs1.w, u1.f.y), cs2.w);
            *(float4*)&S.low[r0][colg * 4] = o;
        }
        {
            float mu = S.mu2[r1], rs = S.rstd2[r1];
            F2 u0, u1; u0.u = acc10; u1.u = acc11;
            float4 o;
            o.x = fmaf(rs, fmaf(-mu, cs1.x, u0.f.x), cs2.x);
            o.y = fmaf(rs, fmaf(-mu, cs1.y, u0.f.y), cs2.y);
            o.z = fmaf(rs, fmaf(-mu, cs1.z, u1.f.x), cs2.z);
            o.w = fmaf(rs, fmaf(-mu, cs1.w, u1.f.y), cs2.w);
            *(float4*)&S.low[r1][colg * 4] = o;
        }
    }
    __syncthreads();

    // ================= P3: Q/K/V/CG GEMM, r=4 x c=8 tiles ========================
    {
        int rowg = t >> 4, colg = t & 15;
        int r0 = rowg * 4;
        int q = colg >> 2, o8 = (colg & 3) * 8;
        ull acc[4][4];
        #pragma unroll
        for (int i = 0; i < 4; i++)
            #pragma unroll
            for (int j = 0; j < 4; j++) acc[i][j] = 0ULL;

        #pragma unroll 4
        for (int k = 0; k < 32; k++) {
            const float* wr = &S.We[k][q * 36 + o8];
            ulonglong2 bA = *(const ulonglong2*)wr;
            ulonglong2 bB = *(const ulonglong2*)(wr + 4);
            #pragma unroll
            for (int i = 0; i < 4; i++) {
                ull ad = dup2(S.low[r0 + i][k]);
                fma2(acc[i][0], ad, bA.x); fma2(acc[i][1], ad, bA.y);
                fma2(acc[i][2], ad, bB.x); fma2(acc[i][3], ad, bB.y);
            }
        }
        // unpack
        float a[4][8];
        #pragma unroll
        for (int i = 0; i < 4; i++)
            #pragma unroll
            for (int jp = 0; jp < 4; jp++) {
                F2 u; u.u = acc[i][jp];
                a[i][2*jp] = u.f.x; a[i][2*jp+1] = u.f.y;
            }
        // per-row sumsq over this matrix's 32 cols (4 colg lanes)
        float rs_[4];
        #pragma unroll
        for (int i = 0; i < 4; i++) {
            float s = 0.f;
            #pragma unroll
            for (int j = 0; j < 8; j++) s = fmaf(a[i][j], a[i][j], s);
            s += __shfl_xor_sync(FULL, s, 1);
            s += __shfl_xor_sync(FULL, s, 2);
            rs_[i] = 1.f / fmaxf(sqrtf(s), 1e-12f);
        }
        float bcv[8];
        *(float4*)&bcv[0] = __ldg((const float4*)(b_cg + o8));
        *(float4*)&bcv[4] = __ldg((const float4*)(b_cg + o8 + 4));

        float kvacc[8];
        #pragma unroll
        for (int j = 0; j < 8; j++) kvacc[j] = 0.f;
        float qav[4][8];
        #pragma unroll
        for (int i = 0; i < 4; i++) {
            float mult = (q <= 1) ? rs_[i] : 1.f;
            #pragma unroll
            for (int j = 0; j < 8; j++) {
                float av = a[i][j] * mult;                       // Qn/Kn or raw V/CG
                float sg = 1.f / (1.f + __expf(-(av + bcv[j]))); // meaningful on CG
                float send = (q == 3) ? sg : av;                 // CG sends sigmoid, K sends Kn
                float recv = __shfl_xor_sync(FULL, send, 12);    // Q<->CG, K<->V
                float prod = av * recv;                          // Q: Qn*cg ; V: V*Kn
                qav[i][j] = prod;
                kvacc[j] += prod;
            }
        }
        if (q == 0) {
            #pragma unroll
            for (int i = 0; i < 4; i++) {
                *(float4*)&S.qa[r0 + i][o8]     = make_float4(qav[i][0], qav[i][1], qav[i][2], qav[i][3]);
                *(float4*)&S.qa[r0 + i][o8 + 4] = make_float4(qav[i][4], qav[i][5], qav[i][6], qav[i][7]);
            }
        }
        if (q == 2) {
            float* kvp = S.kvgate;
            *(float4*)&kvp[rowg * 36 + o8]     = make_float4(kvacc[0], kvacc[1], kvacc[2], kvacc[3]);
            *(float4*)&kvp[rowg * 36 + o8 + 4] = make_float4(kvacc[4], kvacc[5], kvacc[6], kvacc[7]);
        }
    }
    __syncthreads();

    // ================= P4: Wg1 partials + global_feat reduce =====================
    {
        int tl = t >> 7, u = t & 127;
        int j = u & 31, ch = u >> 5, i0 = ch * 64;
        float s = 0.f;
        #pragma unroll 4
        for (int i = 0; i < 64; i++)
            s = fmaf(S.gin[tl][i0 + i], __ldg(Wg1 + (i0 + i) * 32 + j), s);
        if (ch == 3)
            s = fmaf(S.gin[tl][256], __ldg(Wg1 + 256 * 32 + j), s);
        S.g1p[tl][ch][j] = s;
    }
    if (t < 64) {
        int tl = t >> 5, r = t & 31;
        float g = 0.f;
        #pragma unroll
        for (int rg = 0; rg < 8; rg++) g += S.kvgate[(tl * 8 + rg) * 36 + r];
        S.gf[tl][r] = g;
    }
    __syncthreads();

    // ================= P5: g1 gelu + qa *= gf ====================================
    if (t < 64) {
        int tl = t >> 5, r = t & 31;
        float s = __ldg(bg1 + r);
        #pragma unroll
        for (int ch = 0; ch < 4; ch++) s += S.g1p[tl][ch][r];
        S.g1[tl][r] = 0.5f * s * (1.f + erff(s * 0.7071067811865475f));
    }
    {
        int row = t >> 2, qg = t & 3, tl = row >> 5;
        float4 v0 = *(const float4*)&S.qa[row][qg * 8];
        float4 v1 = *(const float4*)&S.qa[row][qg * 8 + 4];
        float4 g0 = *(const float4*)&S.gf[tl][qg * 8];
        float4 g1q = *(const float4*)&S.gf[tl][qg * 8 + 4];
        v0.x *= g0.x; v0.y *= g0.y; v0.z *= g0.z; v0.w *= g0.w;
        v1.x *= g1q.x; v1.y *= g1q.y; v1.z *= g1q.z; v1.w *= g1q.w;
        *(float4*)&S.qa[row][qg * 8]     = v0;
        *(float4*)&S.qa[row][qg * 8 + 4] = v1;
    }
    __syncthreads();

    // ================= P6: gate2 sigmoid =========================================
    {
        int tl = t >> 7, u = t & 127;
        float s = __ldg(bg2 + u);
        #pragma unroll 8
        for (int j = 0; j < 32; j++)
            s = fmaf(S.g1[tl][j], __ldg(Wg2 + j * 128 + u), s);
        S.kvgate[tl * 144 + (u >> 5) * 36 + (u & 31)] = 1.f / (1.f + __expf(-s));
    }
    __syncthreads();

    // ================= P7: up-proj + gated residual, r=4 x c=8 ===================
    {
        int rowg = t >> 4, colg = t & 15;
        int r0 = rowg * 4;
        int q = colg >> 2, o8 = (colg & 3) * 8;
        int tl = r0 >> 5, cc = r0 & 31;
        ull acc[4][4];
        #pragma unroll
        for (int i = 0; i < 4; i++)
            #pragma unroll
            for (int j = 0; j < 4; j++) acc[i][j] = 0ULL;

        #pragma unroll 4
        for (int k = 0; k < 32; k++) {
            const float* wr = &S.Wu[k][q * 36 + o8];
            ulonglong2 bA = *(const ulonglong2*)wr;
            ulonglong2 bB = *(const ulonglong2*)(wr + 4);
            #pragma unroll
            for (int i = 0; i < 4; i++) {
                ull ad = dup2(S.qa[r0 + i][k]);
                fma2(acc[i][0], ad, bA.x); fma2(acc[i][1], ad, bA.y);
                fma2(acc[i][2], ad, bB.x); fma2(acc[i][3], ad, bB.y);
            }
        }
        const float* gr = &S.kvgate[tl * 144 + q * 36 + o8];
        float4 gt0 = *(const float4*)gr;
        float4 gt1 = *(const float4*)(gr + 4);
        float4 bu0 = __ldg((const float4*)(b_up + q * 32 + o8));
        float4 bu1 = __ldg((const float4*)(b_up + q * 32 + o8 + 4));
        #pragma unroll
        for (int i = 0; i < 4; i++) {
            F2 u0, u1, u2, u3;
            u0.u = acc[i][0]; u1.u = acc[i][1]; u2.u = acc[i][2]; u3.u = acc[i][3];
            float* hp = &S.h[tl][cc + i][q * 32 + o8];
            float4 h0 = *(const float4*)hp;
            float4 h1 = *(const float4*)(hp + 4);
            float4 o0, o1;
            o0.x = fmaf(gt0.x, u0.f.x + bu0.x, h0.x);
            o0.y = fmaf(gt0.y, u0.f.y + bu0.y, h0.y);
            o0.z = fmaf(gt0.z, u1.f.x + bu0.z, h0.z);
            o0.w = fmaf(gt0.w, u1.f.y + bu0.w, h0.w);
            o1.x = fmaf(gt1.x, u2.f.x + bu1.x, h1.x);
            o1.y = fmaf(gt1.y, u2.f.y + bu1.y, h1.y);
            o1.z = fmaf(gt1.z, u3.f.x + bu1.z, h1.z);
            o1.w = fmaf(gt1.w, u3.f.y + bu1.w, h1.w);
            *(float4*)hp       = o0;
            *(float4*)(hp + 4) = o1;
        }
    }
    __syncthreads();

    // ================= P8: coalesced store =======================================
    {
        float4* out4 = (float4*)out;
        #pragma unroll
        for (int i = 0; i < 8; i++) {
            int g = i * NT + t;
            int tl = g >> 10, loc = g & 1023;
            int c = loc >> 5, v = loc & 31;
            int bp = blockIdx.x * 2 + tl;
            int b = bp >> 8, p = bp & 255;
            out4[(b * 8192 + c * 256 + p) * 32 + v] = *(const float4*)&S.h[tl][c][v * 4];
        }
    }
}

extern "C" void kernel_launch(void* const* d_in, const int* in_sizes, int n_in,
                              void* d_out, int out_size)
{
    const float* x      = (const float*)d_in[0];
    const float* gamma  = (const float*)d_in[1];
    const float* beta   = (const float*)d_in[2];
    const float* W_down = (const float*)d_in[3];
    const float* b_down = (const float*)d_in[4];
    const float* W_q    = (const float*)d_in[5];
    const float* W_k    = (const float*)d_in[6];
    const float* W_v    = (const float*)d_in[7];
    const float* W_cg   = (const float*)d_in[8];
    const float* b_cg   = (const float*)d_in[9];
    const float* W_up   = (const float*)d_in[10];
    const float* b_up   = (const float*)d_in[11];
    const float* Wg1    = (const float*)d_in[12];
    const float* bg1    = (const float*)d_in[13];
    const float* Wg2    = (const float*)d_in[14];
    const float* bg2    = (const float*)d_in[15];

    cudaFuncSetAttribute(hydra_kernel, cudaFuncAttributeMaxDynamicSharedMemorySize,
                         (int)sizeof(Smem));
    hydra_kernel<<<GRID, NT, sizeof(Smem)>>>(x, gamma, beta, W_down, b_down,
                                             W_q, W_k, W_v, W_cg, b_cg,
                                             W_up, b_up, Wg1, bg1, Wg2, bg2,
                                             (float*)d_out);
}

// round 17
// speedup vs baseline: 1.6875x; 1.1723x over previous
#include <cuda_runtime.h>
#include <math.h>

// HydraChannelMixer — GB300 sm_103a, round 17.
// 2 tiles [C=32, D=128] per 256-thread block (grid 8192), SMEM-staged weights,
// 2-D register-tiled GEMMs with packed fma.rn.f32x2, A-operand register chunking.

#define NT   256
#define GRID 8192

typedef unsigned long long ull;
union F2 { ull u; float2 f; };

__device__ __forceinline__ ull dup2(float a) {
    ull r; asm("mov.b64 %0, {%1, %1};" : "=l"(r) : "f"(a)); return r;
}
__device__ __forceinline__ void fma2(ull& d, ull a, ull b) {
    asm("fma.rn.f32x2 %0, %1, %2, %0;" : "+l"(d) : "l"(a), "l"(b));
}

struct __align__(16) Smem {
    float Wd[128][32];    // gamma-folded W_down (k-major)
    float We[32][144];    // [k][q*36+o], q in {Q,K,V,CG}
    float Wu[32][144];    // [k][q*36+o], W_up col q*32+o
    float cS1[32];        // sum_d gamma*W_down
    float cS2f[32];       // sum_d beta*W_down + b_down
    float h[2][32][132];  // raw h tiles
    float low[64][36];    // h_low rows; cp partials pre-P2; g1p partials in P4/P5
    float qa[64][36];     // Qn*cg rows, later scaled by gf
    float kvgate[576];    // kvp[16][36] (P3-P4), then gate[2][144] (P6-P7)
    float gin[2][260];    // gate-MLP input
    float mu2[64];
    float rstd2[64];
    float gf[2][32];      // global_feat
    float g1[2][32];
};

__global__ void __launch_bounds__(NT, 2) hydra_kernel(
    const float* __restrict__ x,
    const float* __restrict__ gamma,
    const float* __restrict__ beta,
    const float* __restrict__ W_down,
    const float* __restrict__ b_down,
    const float* __restrict__ W_q,
    const float* __restrict__ W_k,
    const float* __restrict__ W_v,
    const float* __restrict__ W_cg,
    const float* __restrict__ b_cg,
    const float* __restrict__ W_up,
    const float* __restrict__ b_up,
    const float* __restrict__ Wg1,
    const float* __restrict__ bg1,
    const float* __restrict__ Wg2,
    const float* __restrict__ bg2,
    float* __restrict__ out)
{
    extern __shared__ __align__(16) char smem_raw[];
    Smem& S = *reinterpret_cast<Smem*>(smem_raw);

    const int t    = threadIdx.x;
    const int lane = t & 31;
    const int w    = t >> 5;
    const unsigned FULL = 0xffffffffu;

    float* cp = &S.low[0][0];   // [2][8][32] cS partials, dead before P2

    // ================= P0: stage weights + both h tiles + cS partials ============
    #pragma unroll
    for (int i = 0; i < 16; i++) {
        int idx = i * NT + t;
        int d = idx >> 5, r = idx & 31;
        S.Wd[d][r] = __ldg(gamma + d) * __ldg(W_down + idx);
    }
    {
        int o  = t & 31;
        int mq = (t >> 5) & 3;      // uniform per warp
        const float* Wm = (mq == 0) ? W_q : (mq == 1) ? W_k : (mq == 2) ? W_v : W_cg;
        #pragma unroll
        for (int i = 0; i < 16; i++) {
            int k = i * 2 + (t >> 7);
            S.We[k][mq * 36 + o] = __ldg(Wm + k * 32 + o);
            S.Wu[k][mq * 36 + o] = __ldg(W_up + k * 128 + mq * 32 + o);
        }
    }
    {
        const float4* x4 = (const float4*)x;
        #pragma unroll
        for (int i = 0; i < 8; i++) {
            int g = i * NT + t;
            int tl = g >> 10, loc = g & 1023;
            int c = loc >> 5, v = loc & 31;
            int bp = blockIdx.x * 2 + tl;
            int b = bp >> 8, p = bp & 255;
            *(float4*)&S.h[tl][c][v * 4] = x4[(b * 8192 + c * 256 + p) * 32 + v];
        }
    }
    {
        int r = t & 31, ch = t >> 5;
        float s1 = 0.f, s2 = 0.f;
        #pragma unroll 4
        for (int dd = 0; dd < 16; dd++) {
            int d = ch * 16 + dd;
            float wv = __ldg(W_down + d * 32 + r);
            s1 = fmaf(__ldg(gamma + d), wv, s1);
            s2 = fmaf(__ldg(beta  + d), wv, s2);
        }
        cp[ch * 32 + r]       = s1;
        cp[256 + ch * 32 + r] = s2;
    }
    __syncthreads();

    // ================= P1: LN row stats (all warps) + channel stats + cS ========
    {   // row stats: each warp 8 rows, 4 lanes per row
        int row  = (w << 3) + (lane >> 2);    // 0..63
        int tl   = row >> 5, c = row & 31;
        int quad = lane & 3;
        float s = 0.f, ss = 0.f;
        #pragma unroll
        for (int i = 0; i < 8; i++) {
            float4 v = *(const float4*)&S.h[tl][c][quad * 32 + i * 4];
            s += v.x + v.y + v.z + v.w;
            ss = fmaf(v.x, v.x, ss); ss = fmaf(v.y, v.y, ss);
            ss = fmaf(v.z, v.z, ss); ss = fmaf(v.w, v.w, ss);
        }
        s  += __shfl_xor_sync(FULL, s, 1);  ss += __shfl_xor_sync(FULL, ss, 1);
        s  += __shfl_xor_sync(FULL, s, 2);  ss += __shfl_xor_sync(FULL, ss, 2);
        if (quad == 0) {
            float mu  = s * 0.0078125f;
            float var = ss * 0.0078125f - mu * mu;
            S.mu2[row]   = mu;
            S.rstd2[row] = rsqrtf(var + 1e-5f);
        }
    }
    {   // channel stats: one (tl, d) per thread
        int tl = t >> 7, d = t & 127;
        float s = 0.f, ss = 0.f, sa = 0.f;
        #pragma unroll 8
        for (int c = 0; c < 32; c++) {
            float v = S.h[tl][c][d];
            s += v; ss = fmaf(v, v, ss); sa += fabsf(v);
        }
        S.gin[tl][d]       = (ss - s * s * 0.03125f) * (1.f / 31.f);
        S.gin[tl][128 + d] = sa * 0.03125f;
        if (d == 0) S.gin[tl][256] = 0.501716659f;   // log(32)/log(1000)
    }
    if (t < 32) {
        float s = 0.f;
        #pragma unroll
        for (int ch = 0; ch < 8; ch++) s += cp[ch * 32 + t];
        S.cS1[t] = s;
    } else if (t < 64) {
        int r = t - 32;
        float s = __ldg(b_down + r);
        #pragma unroll
        for (int ch = 0; ch < 8; ch++) s += cp[256 + ch * 32 + r];
        S.cS2f[r] = s;
    }
    __syncthreads();

    // ================= P2: down-proj (LN folded), r=2 x c=4 tiles ================
    {
        int rowg = t >> 3, colg = t & 7;
        int r0 = rowg * 2, r1 = r0 + 1;
        int tl = rowg >> 4;
        int cA = r0 & 31, cB = cA + 1;
        ull acc00 = 0, acc01 = 0, acc10 = 0, acc11 = 0;
        #pragma unroll
        for (int kc = 0; kc < 16; kc++) {
            float a0[8], a1[8];
            *(float4*)&a0[0] = *(const float4*)&S.h[tl][cA][kc * 8];
            *(float4*)&a0[4] = *(const float4*)&S.h[tl][cA][kc * 8 + 4];
            *(float4*)&a1[0] = *(const float4*)&S.h[tl][cB][kc * 8];
            *(float4*)&a1[4] = *(const float4*)&S.h[tl][cB][kc * 8 + 4];
            #pragma unroll
            for (int kk = 0; kk < 8; kk++) {
                ulonglong2 b2 = *(const ulonglong2*)&S.Wd[kc * 8 + kk][colg * 4];
                ull d0 = dup2(a0[kk]), d1 = dup2(a1[kk]);
                fma2(acc00, d0, b2.x); fma2(acc01, d0, b2.y);
                fma2(acc10, d1, b2.x); fma2(acc11, d1, b2.y);
            }
        }
        float4 cs1 = *(const float4*)&S.cS1[colg * 4];
        float4 cs2 = *(const float4*)&S.cS2f[colg * 4];
        {
            float mu = S.mu2[r0], rs = S.rstd2[r0];
            F2 u0, u1; u0.u = acc00; u1.u = acc01;
            float4 o;
            o.x = fmaf(rs, fmaf(-mu, cs1.x, u0.f.x), cs2.x);
            o.y = fmaf(rs, fmaf(-mu, cs1.y, u0.f.y), cs2.y);
            o.z = fmaf(rs, fmaf(-mu, cs1.z, u1.f.x), cs2.z);
            o.w = fmaf(rs, fmaf(-mu, cs1.w, u1.f.y), cs2.w);
            *(float4*)&S.low[r0][colg * 4] = o;
        }
        {
            float mu = S.mu2[r1], rs = S.rstd2[r1];
            F2 u0, u1; u0.u = acc10; u1.u = acc11;
            float4 o;
            o.x = fmaf(rs, fmaf(-mu, cs1.x, u0.f.x), cs2.x);
            o.y = fmaf(rs, fmaf(-mu, cs1.y, u0.f.y), cs2.y);
            o.z = fmaf(rs, fmaf(-mu, cs1.z, u1.f.x), cs2.z);
            o.w = fmaf(rs, fmaf(-mu, cs1.w, u1.f.y), cs2.w);
            *(float4*)&S.low[r1][colg * 4] = o;
        }
    }
    __syncthreads();

    // ================= P3: Q/K/V/CG GEMM, r=4 x c=8, A reg-chunked ==============
    {
        int rowg = t >> 4, colg = t & 15;
        int r0 = rowg * 4;
        int q = colg >> 2, o8 = (colg & 3) * 8;
        ull acc[4][4];
        #pragma unroll
        for (int i = 0; i < 4; i++)
            #pragma unroll
            for (int j = 0; j < 4; j++) acc[i][j] = 0ULL;

        #pragma unroll
        for (int kc = 0; kc < 8; kc++) {
            float a[4][4];
            #pragma unroll
            for (int i = 0; i < 4; i++)
                *(float4*)a[i] = *(const float4*)&S.low[r0 + i][kc * 4];
            #pragma unroll
            for (int kk = 0; kk < 4; kk++) {
                const float* wr = &S.We[kc * 4 + kk][q * 36 + o8];
                ulonglong2 bA = *(const ulonglong2*)wr;
                ulonglong2 bB = *(const ulonglong2*)(wr + 4);
                #pragma unroll
                for (int i = 0; i < 4; i++) {
                    ull ad = dup2(a[i][kk]);
                    fma2(acc[i][0], ad, bA.x); fma2(acc[i][1], ad, bA.y);
                    fma2(acc[i][2], ad, bB.x); fma2(acc[i][3], ad, bB.y);
                }
            }
        }
        // unpack
        float a[4][8];
        #pragma unroll
        for (int i = 0; i < 4; i++)
            #pragma unroll
            for (int jp = 0; jp < 4; jp++) {
                F2 u; u.u = acc[i][jp];
                a[i][2*jp] = u.f.x; a[i][2*jp+1] = u.f.y;
            }
        // per-row sumsq over this matrix's 32 cols (4 colg lanes)
        float rs_[4];
        #pragma unroll
        for (int i = 0; i < 4; i++) {
            float s = 0.f;
            #pragma unroll
            for (int j = 0; j < 8; j++) s = fmaf(a[i][j], a[i][j], s);
            s += __shfl_xor_sync(FULL, s, 1);
            s += __shfl_xor_sync(FULL, s, 2);
            rs_[i] = 1.f / fmaxf(sqrtf(s), 1e-12f);
        }
        float bcv[8];
        *(float4*)&bcv[0] = __ldg((const float4*)(b_cg + o8));
        *(float4*)&bcv[4] = __ldg((const float4*)(b_cg + o8 + 4));

        float kvacc[8];
        #pragma unroll
        for (int j = 0; j < 8; j++) kvacc[j] = 0.f;
        float qav[4][8];
        #pragma unroll
        for (int i = 0; i < 4; i++) {
            float mult = (q <= 1) ? rs_[i] : 1.f;
            #pragma unroll
            for (int j = 0; j < 8; j++) {
                float av = a[i][j] * mult;                       // Qn/Kn or raw V/CG
                float sg = 1.f / (1.f + __expf(-(av + bcv[j]))); // meaningful on CG
                float send = (q == 3) ? sg : av;                 // CG sends sigmoid, K sends Kn
                float recv = __shfl_xor_sync(FULL, send, 12);    // Q<->CG, K<->V
                float prod = av * recv;                          // Q: Qn*cg ; V: V*Kn
                qav[i][j] = prod;
                kvacc[j] += prod;
            }
        }
        if (q == 0) {
            #pragma unroll
            for (int i = 0; i < 4; i++) {
                *(float4*)&S.qa[r0 + i][o8]     = make_float4(qav[i][0], qav[i][1], qav[i][2], qav[i][3]);
                *(float4*)&S.qa[r0 + i][o8 + 4] = make_float4(qav[i][4], qav[i][5], qav[i][6], qav[i][7]);
            }
        }
        if (q == 2) {
            float* kvp = S.kvgate;
            *(float4*)&kvp[rowg * 36 + o8]     = make_float4(kvacc[0], kvacc[1], kvacc[2], kvacc[3]);
            *(float4*)&kvp[rowg * 36 + o8 + 4] = make_float4(kvacc[4], kvacc[5], kvacc[6], kvacc[7]);
        }
    }
    __syncthreads();

    // ================= P4: Wg1 (float4), partials into dead low; gf reduce ======
    {
        int tl = t >> 7, u = t & 127;
        int ch = u >> 3;            // 0..15, 16 i's each
        int jg = u & 7;             // j = jg*4
        int i0 = ch * 16;
        float4 acc = make_float4(0.f, 0.f, 0.f, 0.f);
        #pragma unroll 4
        for (int i = 0; i < 16; i++) {
            float gi = S.gin[tl][i0 + i];
            float4 wv = __ldg((const float4*)(Wg1 + (i0 + i) * 32 + jg * 4));
            acc.x = fmaf(gi, wv.x, acc.x);
            acc.y = fmaf(gi, wv.y, acc.y);
            acc.z = fmaf(gi, wv.z, acc.z);
            acc.w = fmaf(gi, wv.w, acc.w);
        }
        if (ch == 15) {
            float gi = S.gin[tl][256];
            float4 wv = __ldg((const float4*)(Wg1 + 256 * 32 + jg * 4));
            acc.x = fmaf(gi, wv.x, acc.x);
            acc.y = fmaf(gi, wv.y, acc.y);
            acc.z = fmaf(gi, wv.z, acc.z);
            acc.w = fmaf(gi, wv.w, acc.w);
        }
        float* g1p = &S.low[0][0];          // overlay [2][16][32] (low dead after P3)
        *(float4*)&g1p[tl * 512 + ch * 32 + jg * 4] = acc;
    }
    if (t < 64) {
        int tl = t >> 5, r = t & 31;
        float g = 0.f;
        #pragma unroll
        for (int rg = 0; rg < 8; rg++) g += S.kvgate[(tl * 8 + rg) * 36 + r];
        S.gf[tl][r] = g;
    }
    __syncthreads();

    // ================= P5: g1 gelu + qa *= gf ====================================
    if (t < 64) {
        int tl = t >> 5, r = t & 31;
        float s = __ldg(bg1 + r);
        const float* g1p = &S.low[0][0];
        #pragma unroll
        for (int ch = 0; ch < 16; ch++) s += g1p[tl * 512 + ch * 32 + r];
        S.g1[tl][r] = 0.5f * s * (1.f + erff(s * 0.7071067811865475f));
    }
    {
        int row = t >> 2, qg = t & 3, tl = row >> 5;
        float4 v0 = *(const float4*)&S.qa[row][qg * 8];
        float4 v1 = *(const float4*)&S.qa[row][qg * 8 + 4];
        float4 g0 = *(const float4*)&S.gf[tl][qg * 8];
        float4 g1q = *(const float4*)&S.gf[tl][qg * 8 + 4];
        v0.x *= g0.x; v0.y *= g0.y; v0.z *= g0.z; v0.w *= g0.w;
        v1.x *= g1q.x; v1.y *= g1q.y; v1.z *= g1q.z; v1.w *= g1q.w;
        *(float4*)&S.qa[row][qg * 8]     = v0;
        *(float4*)&S.qa[row][qg * 8 + 4] = v1;
    }
    __syncthreads();

    // ================= P6: gate2 sigmoid (g1 via float4 broadcasts) =============
    {
        int tl = t >> 7, u = t & 127;
        float s = __ldg(bg2 + u);
        #pragma unroll
        for (int jc = 0; jc < 8; jc++) {
            float4 g = *(const float4*)&S.g1[tl][jc * 4];
            s = fmaf(g.x, __ldg(Wg2 + (jc * 4 + 0) * 128 + u), s);
            s = fmaf(g.y, __ldg(Wg2 + (jc * 4 + 1) * 128 + u), s);
            s = fmaf(g.z, __ldg(Wg2 + (jc * 4 + 2) * 128 + u), s);
            s = fmaf(g.w, __ldg(Wg2 + (jc * 4 + 3) * 128 + u), s);
        }
        S.kvgate[tl * 144 + (u >> 5) * 36 + (u & 31)] = 1.f / (1.f + __expf(-s));
    }
    __syncthreads();

    // ================= P7: up-proj + gated residual, r=4 x c=8, A reg-chunked ===
    {
        int rowg = t >> 4, colg = t & 15;
        int r0 = rowg * 4;
        int q = colg >> 2, o8 = (colg & 3) * 8;
        int tl = r0 >> 5, cc = r0 & 31;
        ull acc[4][4];
        #pragma unroll
        for (int i = 0; i < 4; i++)
            #pragma unroll
            for (int j = 0; j < 4; j++) acc[i][j] = 0ULL;

        #pragma unroll
        for (int kc = 0; kc < 8; kc++) {
            float a[4][4];
            #pragma unroll
            for (int i = 0; i < 4; i++)
                *(float4*)a[i] = *(const float4*)&S.qa[r0 + i][kc * 4];
            #pragma unroll
            for (int kk = 0; kk < 4; kk++) {
                const float* wr = &S.Wu[kc * 4 + kk][q * 36 + o8];
                ulonglong2 bA = *(const ulonglong2*)wr;
                ulonglong2 bB = *(const ulonglong2*)(wr + 4);
                #pragma unroll
                for (int i = 0; i < 4; i++) {
                    ull ad = dup2(a[i][kk]);
                    fma2(acc[i][0], ad, bA.x); fma2(acc[i][1], ad, bA.y);
                    fma2(acc[i][2], ad, bB.x); fma2(acc[i][3], ad, bB.y);
                }
            }
        }
        const float* gr = &S.kvgate[tl * 144 + q * 36 + o8];
        float4 gt0 = *(const float4*)gr;
        float4 gt1 = *(const float4*)(gr + 4);
        float4 bu0 = __ldg((const float4*)(b_up + q * 32 + o8));
        float4 bu1 = __ldg((const float4*)(b_up + q * 32 + o8 + 4));
        #pragma unroll
        for (int i = 0; i < 4; i++) {
            F2 u0, u1, u2, u3;
            u0.u = acc[i][0]; u1.u = acc[i][1]; u2.u = acc[i][2]; u3.u = acc[i][3];
            float* hp = &S.h[tl][cc + i][q * 32 + o8];
            float4 h0 = *(const float4*)hp;
            float4 h1 = *(const float4*)(hp + 4);
            float4 o0, o1;
            o0.x = fmaf(gt0.x, u0.f.x + bu0.x, h0.x);
            o0.y = fmaf(gt0.y, u0.f.y + bu0.y, h0.y);
            o0.z = fmaf(gt0.z, u1.f.x + bu0.z, h0.z);
            o0.w = fmaf(gt0.w, u1.f.y + bu0.w, h0.w);
            o1.x = fmaf(gt1.x, u2.f.x + bu1.x, h1.x);
            o1.y = fmaf(gt1.y, u2.f.y + bu1.y, h1.y);
            o1.z = fmaf(gt1.z, u3.f.x + bu1.z, h1.z);
            o1.w = fmaf(gt1.w, u3.f.y + bu1.w, h1.w);
            *(float4*)hp       = o0;
            *(float4*)(hp + 4) = o1;
        }
    }
    __syncthreads();

    // ================= P8: coalesced store =======================================
    {
        float4* out4 = (float4*)out;
        #pragma unroll
        for (int i = 0; i < 8; i++) {
            int g = i * NT + t;
            int tl = g >> 10, loc = g & 1023;
            int c = loc >> 5, v = loc & 31;
            int bp = blockIdx.x * 2 + tl;
            int b = bp >> 8, p = bp & 255;
            out4[(b * 8192 + c * 256 + p) * 32 + v] = *(const float4*)&S.h[tl][c][v * 4];
        }
    }
}

extern "C" void kernel_launch(void* const* d_in, const int* in_sizes, int n_in,
                              void* d_out, int out_size)
{
    const float* x      = (const float*)d_in[0];
    const float* gamma  = (const float*)d_in[1];
    const float* beta   = (const float*)d_in[2];
    const float* W_down = (const float*)d_in[3];
    const float* b_down = (const float*)d_in[4];
    const float* W_q    = (const float*)d_in[5];
    const float* W_k    = (const float*)d_in[6];
    const float* W_v    = (const float*)d_in[7];
    const float* W_cg   = (const float*)d_in[8];
    const float* b_cg   = (const float*)d_in[9];
    const float* W_up   = (const float*)d_in[10];
    const float* b_up   = (const float*)d_in[11];
    const float* Wg1    = (const float*)d_in[12];
    const float* bg1    = (const float*)d_in[13];
    const float* Wg2    = (const float*)d_in[14];
    const float* bg2    = (const float*)d_in[15];

    cudaFuncSetAttribute(hydra_kernel, cudaFuncAttributeMaxDynamicSharedMemorySize,
                         (int)sizeof(Smem));
    hydra_kernel<<<GRID, NT, sizeof(Smem)>>>(x, gamma, beta, W_down, b_down,
                                             W_q, W_k, W_v, W_cg, b_cg,
                                             W_up, b_up, Wg1, bg1, Wg2, bg2,
                                             (float*)d_out);
}